// round 12
// baseline (speedup 1.0000x reference)
#include <cuda_runtime.h>
#include <cuda_fp16.h>
#include <cstdint>
#include <cstddef>

// ---------------------------------------------------------------------------
// out[B,O] = (x + sparse_pert) @ W + b
//          = x @ W + b + coeff * u[r] * W[idx[r], :]   (u = bitflip(g) - g)
// B=4096, F=16384, O=256, fp32.
//
// R12: test fp16-ACCUMULATE mma (m16n8k16.f16) at hoped 2x rate of the
// fp32-acc fallback (measured hard cap ~16cyc/SMSP across R5-R11).
// fp16 partial sums kept for 4-stage chunks (K=128), promoted to fp32
// registers every 4 stages (error contribution ~7e-5). BM=64, SPLITK=2
// keeps 128 CTAs (single wave) and register fit at 256 threads.
// ---------------------------------------------------------------------------

namespace {
constexpr int Bm = 4096;
constexpr int Fk = 16384;
constexpr int On = 256;

constexpr int BM = 64;
constexpr int BK = 32;
constexpr int SPLITK = 2;
constexpr int K_PER_CTA = Fk / SPLITK;     // 8192
constexpr int NT = K_PER_CTA / BK;         // 256 stages
constexpr int STAGES = 5;
constexpr int NTHREADS = 256;
constexpr int CHUNK = 4;                   // stages per fp16->fp32 promotion

// SMEM layout (bytes)
constexpr int RAWA_STAGE = BM * BK * 4;            // 8192 (fp32 x tile)
constexpr int BROW_PITCH = 80;                     // 64B data + 16B pad
constexpr int B_STAGE = 256 * BROW_PITCH;          // 20480
constexpr int ACONV = BM * BROW_PITCH;             // 5120 (x2 parity buffers)

constexpr int OFF_RAWA = 0;                                        // 40960
constexpr int OFF_B    = OFF_RAWA + STAGES * RAWA_STAGE;           // 40960
constexpr int OFF_AC   = OFF_B + STAGES * B_STAGE;                 // 143360
constexpr int SMEM_TOTAL = OFF_AC + 2 * ACONV;                     // 153600
}  // namespace

// Pre-transposed W: Wt[n, k] fp16 (8 MB). Static scratch.
__device__ __align__(16) __half g_Wt[(size_t)On * Fk];

// ---------------------------- helpers --------------------------------------
__device__ __forceinline__ uint32_t smem_u32(const void* p) {
    uint32_t a;
    asm("{ .reg .u64 t; cvta.to.shared.u64 t, %1; cvt.u32.u64 %0, t; }"
        : "=r"(a) : "l"(p));
    return a;
}

__device__ __forceinline__ void cp_async16(void* dst, const void* src) {
    asm volatile("cp.async.cg.shared.global [%0], [%1], 16;"
                 :: "r"(smem_u32(dst)), "l"(src) : "memory");
}
__device__ __forceinline__ void cp_commit() {
    asm volatile("cp.async.commit_group;" ::: "memory");
}
template <int N>
__device__ __forceinline__ void cp_wait() {
    asm volatile("cp.async.wait_group %0;" :: "n"(N) : "memory");
}

// pack f16(x1):f16(x0), x0 in low half
__device__ __forceinline__ uint32_t cvt_f16x2(float x1, float x0) {
    uint32_t d;
    asm("cvt.rn.f16x2.f32 %0, %1, %2;" : "=r"(d) : "f"(x1), "f"(x0));
    return d;
}

__device__ __forceinline__ void ldsm_x4(uint32_t r[4], uint32_t addr) {
    asm volatile(
        "ldmatrix.sync.aligned.m8n8.x4.shared.b16 {%0,%1,%2,%3}, [%4];"
        : "=r"(r[0]), "=r"(r[1]), "=r"(r[2]), "=r"(r[3]) : "r"(addr));
}

// fp16-accumulate variant: C/D are 2x b32 (f16x2)
__device__ __forceinline__ void mma_f16acc(uint32_t c[2], const uint32_t a[4],
                                           const uint32_t b[2]) {
    asm volatile(
        "mma.sync.aligned.m16n8k16.row.col.f16.f16.f16.f16 "
        "{%0,%1},{%2,%3,%4,%5},{%6,%7},{%0,%1};"
        : "+r"(c[0]), "+r"(c[1])
        : "r"(a[0]), "r"(a[1]), "r"(a[2]), "r"(a[3]), "r"(b[0]), "r"(b[1]));
}

// ------------------- kernel 1: W transpose to fp16 -------------------------
__global__ void prep_w_kernel(const float* __restrict__ W) {
    __shared__ float t[32][33];
    int n0 = blockIdx.x * 32;
    int k0 = blockIdx.y * 32;
    int tx = threadIdx.x, ty = threadIdx.y;
#pragma unroll
    for (int j = 0; j < 4; j++) {
        int k = k0 + ty + j * 8;
        t[ty + j * 8][tx] = W[(size_t)k * On + n0 + tx];
    }
    __syncthreads();
#pragma unroll
    for (int j = 0; j < 4; j++) {
        int n = n0 + ty + j * 8;
        float v = t[tx][ty + j * 8];
        g_Wt[(size_t)n * Fk + k0 + tx] = __float2half_rn(v);
    }
}

// ------------ kernel 2: fused init + split-K fp16 mma.sync GEMM ------------
__global__ void __launch_bounds__(NTHREADS, 1)
gemm_kernel(const float* __restrict__ x, const float* __restrict__ W,
            const float* __restrict__ b, const float* __restrict__ coeff,
            const int* __restrict__ idx, const int* __restrict__ bitpos,
            float* __restrict__ out) {
    extern __shared__ char smem[];
    __shared__ float us[32];
    char* rawA = smem + OFF_RAWA;
    char* BS   = smem + OFF_B;
    char* Ac   = smem + OFF_AC;   // 2 parity buffers of ACONV bytes

    const int tid = threadIdx.x;
    const int lane = tid & 31, w = tid >> 5;
    const int wm = w & 1, wn = w >> 1;       // warp grid 2(M) x 4(N), 32x64 tile
    const int g = lane >> 2, q = lane & 3;

    const int m0 = blockIdx.x * BM;
    const int z  = blockIdx.z;
    const int kbase = z * K_PER_CTA;

    // ---- fused init: rows [m0+32z, m0+32z+32) of out = b + coeff*u*W[idx]
    // Safe: grid=128 CTAs <= 148 SMs at occ 1 -> single wave; inits complete
    // ~1us after launch, first epilogue atomic lands far later.
    {
        int r0 = m0 + z * 32;
        if (tid < 32) {
            int r = r0 + tid;
            int j = idx[r];
            float gg = x[(size_t)r * Fk + j];
            int gi = __float_as_int(gg) ^ (1 << bitpos[r]);
            us[tid] = (__int_as_float(gi) - gg) * coeff[0];
        }
        __syncthreads();
#pragma unroll
        for (int i = 0; i < 32; i++) {
            int e = tid + i * NTHREADS;
            int rr = e >> 8, c = e & 255;
            int r = r0 + rr;
            out[(size_t)r * On + c] =
                b[c] + us[rr] * W[(size_t)idx[r] * On + c];
        }
    }

    // ldmatrix per-lane address components (row within 16, k-16B half)
    const int lrow = lane & 15;
    const int lk16 = (lane >> 4) * 16;

    float acc[2][8][4];                // fp32 master accumulators
#pragma unroll
    for (int i = 0; i < 2; i++)
#pragma unroll
        for (int j = 0; j < 8; j++)
#pragma unroll
            for (int r = 0; r < 4; r++) acc[i][j][r] = 0.0f;

    uint32_t facc[2][8][2];            // fp16 chunk accumulators (f16x2 pairs)
#pragma unroll
    for (int i = 0; i < 2; i++)
#pragma unroll
        for (int j = 0; j < 8; j++) { facc[i][j][0] = 0u; facc[i][j][1] = 0u; }

    // ---- stage loader (always commits one group) ----
    auto issue = [&](int kt, int slot) {
        if (kt < NT) {
            const float* xg = x + (size_t)m0 * Fk + kbase + kt * BK;
            char* ra = rawA + slot * RAWA_STAGE;
#pragma unroll
            for (int i = 0; i < 2; i++) {
                int ch = tid + i * NTHREADS;      // 0..511
                int row = ch >> 3, sub = ch & 7;  // row 0..63
                int phys = sub ^ (row & 7);       // XOR swizzle (bank-free reads)
                cp_async16(ra + row * 128 + phys * 16,
                           xg + (size_t)row * Fk + sub * 4);
            }
            const __half* wt = g_Wt + kbase + kt * BK;
            char* bs = BS + slot * B_STAGE;
#pragma unroll
            for (int i = 0; i < 4; i++) {
                int ch = tid + i * NTHREADS;      // 0..1023
                int row = ch >> 2, sub = ch & 3;  // row 0..255
                cp_async16(bs + row * BROW_PITCH + sub * 16,
                           wt + (size_t)row * Fk + sub * 8);
            }
        }
        cp_commit();
    };

    // convert-thread mapping: 8 floats (2 x float4) per thread, 64 rows
    const int crow = tid >> 2;              // 0..63
    const int cq   = tid & 3;               // quarter of the 32-float row

    auto convert = [&](int k) {             // rawA slot k%5 -> Ac[k&1]
        const char* ra = rawA + (k % STAGES) * RAWA_STAGE;
        char* dst = Ac + (k & 1) * ACONV;
        uint32_t pk[4];
#pragma unroll
        for (int i = 0; i < 2; i++) {
            int phys = (cq * 2 + i) ^ (crow & 7);
            float4 v = *(const float4*)(ra + crow * 128 + phys * 16);
            pk[i * 2]     = cvt_f16x2(v.y, v.x);
            pk[i * 2 + 1] = cvt_f16x2(v.w, v.z);
        }
        *(uint4*)(dst + crow * BROW_PITCH + cq * 16) =
            make_uint4(pk[0], pk[1], pk[2], pk[3]);
    };

    // promote fp16 chunk accumulators into fp32 masters, zero them
    auto promote = [&]() {
#pragma unroll
        for (int mt = 0; mt < 2; mt++)
#pragma unroll
            for (int nt = 0; nt < 8; nt++) {
                float2 f0 = __half22float2(
                    *reinterpret_cast<__half2*>(&facc[mt][nt][0]));
                float2 f1 = __half22float2(
                    *reinterpret_cast<__half2*>(&facc[mt][nt][1]));
                acc[mt][nt][0] += f0.x;
                acc[mt][nt][1] += f0.y;
                acc[mt][nt][2] += f1.x;
                acc[mt][nt][3] += f1.y;
                facc[mt][nt][0] = 0u;
                facc[mt][nt][1] = 0u;
            }
    };

    // ---- prologue: 4 groups in flight, convert stage 0 ----
    issue(0, 0); issue(1, 1); issue(2, 2); issue(3, 3);
    cp_wait<3>();            // group 0 complete
    __syncthreads();         // visible to all
    convert(0);              // Ac[0] <- stage 0

    // ---- mainloop: ONE barrier per stage; convert(kt+1) overlaps MMA(kt) --
    int pslot = 4;           // slot for prefetch stage kt+4
    for (int kt = 0; kt < NT; kt++) {
        cp_wait<2>();        // committed 4+kt; group kt+1 complete
        __syncthreads();     // loads visible; prev MMA+convert done (reuse)

        issue(kt + 4, pslot);
        if (++pslot == STAGES) pslot = 0;

        // MMA on stage kt (Ac[kt&1], BS slot kt%5), fp16 accumulate
        const uint32_t aBase = smem_u32(Ac) + (kt & 1) * ACONV +
            (wm * 32 + lrow) * BROW_PITCH + lk16;
        const uint32_t bBase = smem_u32(BS) + (kt % STAGES) * B_STAGE +
            (wn * 64 + lrow) * BROW_PITCH + lk16;
#pragma unroll
        for (int kk = 0; kk < 2; kk++) {
            uint32_t af[2][4];
#pragma unroll
            for (int mt = 0; mt < 2; mt++)
                ldsm_x4(af[mt], aBase + mt * 16 * BROW_PITCH + kk * 32);
            uint32_t bf[8][2];
#pragma unroll
            for (int p = 0; p < 4; p++) {
                uint32_t r[4];
                ldsm_x4(r, bBase + p * 16 * BROW_PITCH + kk * 32);
                bf[2 * p][0] = r[0]; bf[2 * p + 1][0] = r[1];
                bf[2 * p][1] = r[2]; bf[2 * p + 1][1] = r[3];
            }
#pragma unroll
            for (int mt = 0; mt < 2; mt++)
#pragma unroll
                for (int nt = 0; nt < 8; nt++)
                    mma_f16acc(facc[mt][nt], af[mt], bf[nt]);
        }

        // convert NEXT stage's A while this stage's MMAs drain
        if (kt + 1 < NT) convert(kt + 1);

        // every CHUNK stages: fold fp16 partials into fp32 (overlaps tensor)
        if ((kt & (CHUNK - 1)) == (CHUNK - 1)) promote();
    }
    // NT % CHUNK == 0 -> last promote already done

    cp_wait<0>();  // drain outstanding cp.async before exit

    // ---- epilogue: atomicAdd into initialized out ----
#pragma unroll
    for (int mt = 0; mt < 2; mt++) {
        int r0 = m0 + wm * 32 + mt * 16 + g;
#pragma unroll
        for (int nt = 0; nt < 8; nt++) {
            int col = wn * 64 + nt * 8 + q * 2;
            float* p0 = out + (size_t)r0 * On + col;
            float* p1 = out + (size_t)(r0 + 8) * On + col;
            atomicAdd(p0,     acc[mt][nt][0]);
            atomicAdd(p0 + 1, acc[mt][nt][1]);
            atomicAdd(p1,     acc[mt][nt][2]);
            atomicAdd(p1 + 1, acc[mt][nt][3]);
        }
    }
}

// ---------------------------------------------------------------------------
extern "C" void kernel_launch(void* const* d_in, const int* in_sizes, int n_in,
                              void* d_out, int out_size) {
    const float* x      = (const float*)d_in[0];
    const float* W      = (const float*)d_in[1];
    const float* b      = (const float*)d_in[2];
    const float* coeff  = (const float*)d_in[3];
    const int*   idx    = (const int*)d_in[4];
    const int*   bitpos = (const int*)d_in[5];
    float* out = (float*)d_out;

    cudaFuncSetAttribute(gemm_kernel,
                         cudaFuncAttributeMaxDynamicSharedMemorySize,
                         SMEM_TOTAL);

    // 1) W -> transposed fp16 scratch
    prep_w_kernel<<<dim3(On / 32, Fk / 32), dim3(32, 8)>>>(W);
    // 2) fused init (rank-1 correction + bias) + split-K GEMM
    gemm_kernel<<<dim3(Bm / BM, 1, SPLITK), NTHREADS, SMEM_TOTAL>>>(
        x, W, b, coeff, idx, bitpos, out);
}

// round 14
// speedup vs baseline: 1.1039x; 1.1039x over previous
#include <cuda_runtime.h>
#include <cuda_fp16.h>
#include <cstdint>
#include <cstddef>

// ---------------------------------------------------------------------------
// out[B,O] = (x + sparse_pert) @ W + b
//          = x @ W + b + coeff * u[r] * W[idx[r], :]   (u = bitflip(g) - g)
// B=4096, F=16384, O=256, fp32.
//
// R13 (resubmit after broker infra failure): R11 structure (fp16 mma, fp32
// acc, 1-barrier pipelined stage) but work spread over ALL 148 SMs: 1024
// units (32 m-tiles x 32 k-chunks of K=512), round-robin to 148 CTAs (max
// 7 units = 112 stages vs 128). Accumulators flushed by fire-and-forget
// atomicAdd at unit boundaries.
// ---------------------------------------------------------------------------

namespace {
constexpr int Bm = 4096;
constexpr int Fk = 16384;
constexpr int On = 256;

constexpr int BM = 128;
constexpr int BK = 32;
constexpr int NCTA = 148;                  // full single wave
constexpr int KCH = 512;                   // K per unit
constexpr int SPU = KCH / BK;              // 16 stages per unit
constexpr int NUNITS = (Bm / BM) * (Fk / KCH);   // 32*32 = 1024
constexpr int STAGES = 5;
constexpr int NTHREADS = 256;

// SMEM layout (bytes)
constexpr int RAWA_STAGE = BM * BK * 4;            // 16384 (fp32 x tile)
constexpr int BROW_PITCH = 80;                     // 64B data + 16B pad
constexpr int B_STAGE = 256 * BROW_PITCH;          // 20480
constexpr int ACONV = BM * BROW_PITCH;             // 10240 (x2 parity)

constexpr int OFF_RAWA = 0;                                        // 81920
constexpr int OFF_B    = OFF_RAWA + STAGES * RAWA_STAGE;           // 81920
constexpr int OFF_AC   = OFF_B + STAGES * B_STAGE;                 // 184320
constexpr int SMEM_TOTAL = OFF_AC + 2 * ACONV;                     // 204800
}  // namespace

// Pre-transposed W: Wt[n, k] fp16 (8 MB). Static scratch.
__device__ __align__(16) __half g_Wt[(size_t)On * Fk];

// ---------------------------- helpers --------------------------------------
__device__ __forceinline__ uint32_t smem_u32(const void* p) {
    uint32_t a;
    asm("{ .reg .u64 t; cvta.to.shared.u64 t, %1; cvt.u32.u64 %0, t; }"
        : "=r"(a) : "l"(p));
    return a;
}

__device__ __forceinline__ void cp_async16(void* dst, const void* src) {
    asm volatile("cp.async.cg.shared.global [%0], [%1], 16;"
                 :: "r"(smem_u32(dst)), "l"(src) : "memory");
}
__device__ __forceinline__ void cp_commit() {
    asm volatile("cp.async.commit_group;" ::: "memory");
}
template <int N>
__device__ __forceinline__ void cp_wait() {
    asm volatile("cp.async.wait_group %0;" :: "n"(N) : "memory");
}

// pack f16(x1):f16(x0), x0 in low half
__device__ __forceinline__ uint32_t cvt_f16x2(float x1, float x0) {
    uint32_t d;
    asm("cvt.rn.f16x2.f32 %0, %1, %2;" : "=r"(d) : "f"(x1), "f"(x0));
    return d;
}

__device__ __forceinline__ void ldsm_x4(uint32_t r[4], uint32_t addr) {
    asm volatile(
        "ldmatrix.sync.aligned.m8n8.x4.shared.b16 {%0,%1,%2,%3}, [%4];"
        : "=r"(r[0]), "=r"(r[1]), "=r"(r[2]), "=r"(r[3]) : "r"(addr));
}

__device__ __forceinline__ void mma_f16(float c[4], const uint32_t a[4],
                                        const uint32_t b[2]) {
    asm volatile(
        "mma.sync.aligned.m16n8k16.row.col.f32.f16.f16.f32 "
        "{%0,%1,%2,%3},{%4,%5,%6,%7},{%8,%9},{%0,%1,%2,%3};"
        : "+f"(c[0]), "+f"(c[1]), "+f"(c[2]), "+f"(c[3])
        : "r"(a[0]), "r"(a[1]), "r"(a[2]), "r"(a[3]), "r"(b[0]), "r"(b[1]));
}

// ------------------- kernel 1: W transpose to fp16 -------------------------
__global__ void prep_w_kernel(const float* __restrict__ W) {
    __shared__ float t[32][33];
    int n0 = blockIdx.x * 32;
    int k0 = blockIdx.y * 32;
    int tx = threadIdx.x, ty = threadIdx.y;
#pragma unroll
    for (int j = 0; j < 4; j++) {
        int k = k0 + ty + j * 8;
        t[ty + j * 8][tx] = W[(size_t)k * On + n0 + tx];
    }
    __syncthreads();
#pragma unroll
    for (int j = 0; j < 4; j++) {
        int n = n0 + ty + j * 8;
        float v = t[tx][ty + j * 8];
        g_Wt[(size_t)n * Fk + k0 + tx] = __float2half_rn(v);
    }
}

// ------------ kernel 2: fused init + unit-scheduled fp16 GEMM --------------
__global__ void __launch_bounds__(NTHREADS, 1)
gemm_kernel(const float* __restrict__ x, const float* __restrict__ W,
            const float* __restrict__ b, const float* __restrict__ coeff,
            const int* __restrict__ idx, const int* __restrict__ bitpos,
            float* __restrict__ out) {
    extern __shared__ char smem[];
    char* rawA = smem + OFF_RAWA;
    char* BS   = smem + OFF_B;
    char* Ac   = smem + OFF_AC;   // 2 parity buffers of ACONV bytes

    const int tid = threadIdx.x;
    const int lane = tid & 31, w = tid >> 5;
    const int wm = w & 1, wn = w >> 1;       // warp grid 2(M) x 4(N), 64x64 tile
    const int g = lane >> 2, q = lane & 3;
    const int c = blockIdx.x;

    // ---- fused init: rows r = c, c+148, ... of out = b + coeff*u*W[idx] ----
    // Single wave (148 CTAs = 148 SMs, occ 1): all inits done ~3us after
    // launch; earliest accumulator flush is ~16 stages (~19us) later.
    {
        float cf = coeff[0];
        for (int r = c; r < Bm; r += NCTA) {
            int j = idx[r];
            float gg = x[(size_t)r * Fk + j];
            int gi = __float_as_int(gg) ^ (1 << bitpos[r]);
            float u = (__int_as_float(gi) - gg) * cf;
            out[(size_t)r * On + tid] = b[tid] + u * W[(size_t)j * On + tid];
        }
    }

    // per-CTA work: units u = c + j*NCTA (j = 0..nu-1), each SPU stages
    const int nu = (NUNITS - c + NCTA - 1) / NCTA;   // 7 or 6
    const int ns = nu * SPU;                         // total stages

    // ldmatrix per-lane address components (row within 16, k-16B half)
    const int lrow = lane & 15;
    const int lk16 = (lane >> 4) * 16;

    float acc[4][8][4];
#pragma unroll
    for (int i = 0; i < 4; i++)
#pragma unroll
        for (int j = 0; j < 8; j++)
#pragma unroll
            for (int r = 0; r < 4; r++) acc[i][j][r] = 0.0f;

    // stage s -> (m0, k0)
    auto stage_addr = [&](int s, int& m0, int& k0) {
        int u = c + (s >> 4) * NCTA;       // global unit
        m0 = (u >> 5) * BM;
        k0 = (u & 31) * KCH + (s & 15) * BK;
    };

    // ---- stage loader (always commits one group) ----
    auto issue = [&](int s, int slot) {
        if (s < ns) {
            int m0, k0; stage_addr(s, m0, k0);
            const float* xg = x + (size_t)m0 * Fk + k0;
            char* ra = rawA + slot * RAWA_STAGE;
#pragma unroll
            for (int i = 0; i < 4; i++) {
                int ch = tid + i * NTHREADS;      // 0..1023
                int row = ch >> 3, sub = ch & 7;
                int phys = sub ^ (row & 7);       // XOR swizzle (bank-free reads)
                cp_async16(ra + row * 128 + phys * 16,
                           xg + (size_t)row * Fk + sub * 4);
            }
            const __half* wt = g_Wt + k0;
            char* bs = BS + slot * B_STAGE;
#pragma unroll
            for (int i = 0; i < 4; i++) {
                int ch = tid + i * NTHREADS;      // 0..1023
                int row = ch >> 2, sub = ch & 3;  // row 0..255
                cp_async16(bs + row * BROW_PITCH + sub * 16,
                           wt + (size_t)row * Fk + sub * 8);
            }
        }
        cp_commit();
    };

    // convert-thread mapping: conflict-free LDS.128 + STS.128 (half-row/thr)
    const int crow = (w & 3) * 32 + lane;   // 0..127
    const int chh  = w >> 2;                // half of the 32-float row

    auto convert = [&](int s) {             // rawA slot s%5 -> Ac[s&1]
        const char* ra = rawA + (s % STAGES) * RAWA_STAGE;
        char* dst = Ac + (s & 1) * ACONV;
        uint32_t pk[8];
#pragma unroll
        for (int i = 0; i < 4; i++) {
            int phys = (chh * 4 + i) ^ (crow & 7);
            float4 v = *(const float4*)(ra + crow * 128 + phys * 16);
            pk[i * 2]     = cvt_f16x2(v.y, v.x);
            pk[i * 2 + 1] = cvt_f16x2(v.w, v.z);
        }
        uint4* d = (uint4*)(dst + crow * BROW_PITCH + chh * 32);
        d[0] = make_uint4(pk[0], pk[1], pk[2], pk[3]);
        d[1] = make_uint4(pk[4], pk[5], pk[6], pk[7]);
    };

    // flush accumulators for the unit whose m-tile starts at m0; re-zero.
    // atomicAdd with unused result -> RED (fire-and-forget), overlaps tensor.
    auto flush = [&](int m0) {
#pragma unroll
        for (int mt = 0; mt < 4; mt++) {
            int r0 = m0 + wm * 64 + mt * 16 + g;
#pragma unroll
            for (int nt = 0; nt < 8; nt++) {
                int col = wn * 64 + nt * 8 + q * 2;
                float* p0 = out + (size_t)r0 * On + col;
                float* p1 = out + (size_t)(r0 + 8) * On + col;
                atomicAdd(p0,     acc[mt][nt][0]);
                atomicAdd(p0 + 1, acc[mt][nt][1]);
                atomicAdd(p1,     acc[mt][nt][2]);
                atomicAdd(p1 + 1, acc[mt][nt][3]);
                acc[mt][nt][0] = 0.0f; acc[mt][nt][1] = 0.0f;
                acc[mt][nt][2] = 0.0f; acc[mt][nt][3] = 0.0f;
            }
        }
    };

    // ---- prologue: 4 groups in flight, convert stage 0 ----
    issue(0, 0); issue(1, 1); issue(2, 2); issue(3, 3);
    cp_wait<3>();            // group 0 complete
    __syncthreads();         // visible to all
    convert(0);              // Ac[0] <- stage 0

    // ---- mainloop: ONE barrier per stage; convert(s+1) overlaps MMA(s) ----
    int pslot = 4;           // slot for prefetch stage s+4
    for (int s = 0; s < ns; s++) {
        cp_wait<2>();        // committed 4+s; group s+1 complete
        __syncthreads();     // loads visible; prev MMA+convert done (reuse)

        issue(s + 4, pslot);
        if (++pslot == STAGES) pslot = 0;

        // MMA on stage s (Ac[s&1], BS slot s%5)
        const uint32_t aBase = smem_u32(Ac) + (s & 1) * ACONV +
            (wm * 64 + lrow) * BROW_PITCH + lk16;
        const uint32_t bBase = smem_u32(BS) + (s % STAGES) * B_STAGE +
            (wn * 64 + lrow) * BROW_PITCH + lk16;
#pragma unroll
        for (int kk = 0; kk < 2; kk++) {
            uint32_t af[4][4];
#pragma unroll
            for (int mt = 0; mt < 4; mt++)
                ldsm_x4(af[mt], aBase + mt * 16 * BROW_PITCH + kk * 32);
            uint32_t bf[8][2];
#pragma unroll
            for (int p = 0; p < 4; p++) {
                uint32_t r[4];
                ldsm_x4(r, bBase + p * 16 * BROW_PITCH + kk * 32);
                bf[2 * p][0] = r[0]; bf[2 * p + 1][0] = r[1];
                bf[2 * p][1] = r[2]; bf[2 * p + 1][1] = r[3];
            }
#pragma unroll
            for (int mt = 0; mt < 4; mt++)
#pragma unroll
                for (int nt = 0; nt < 8; nt++)
                    mma_f16(acc[mt][nt], af[mt], bf[nt]);
        }

        // convert NEXT stage's A while this stage's MMAs drain
        if (s + 1 < ns) convert(s + 1);

        // end of unit: flush accumulators for this unit's m-tile
        if ((s & (SPU - 1)) == SPU - 1) {
            int u = c + (s >> 4) * NCTA;
            flush((u >> 5) * BM);
        }
    }

    cp_wait<0>();  // drain outstanding cp.async before exit
}

// ---------------------------------------------------------------------------
extern "C" void kernel_launch(void* const* d_in, const int* in_sizes, int n_in,
                              void* d_out, int out_size) {
    const float* x      = (const float*)d_in[0];
    const float* W      = (const float*)d_in[1];
    const float* b      = (const float*)d_in[2];
    const float* coeff  = (const float*)d_in[3];
    const int*   idx    = (const int*)d_in[4];
    const int*   bitpos = (const int*)d_in[5];
    float* out = (float*)d_out;

    cudaFuncSetAttribute(gemm_kernel,
                         cudaFuncAttributeMaxDynamicSharedMemorySize,
                         SMEM_TOTAL);

    // 1) W -> transposed fp16 scratch
    prep_w_kernel<<<dim3(On / 32, Fk / 32), dim3(32, 8)>>>(W);
    // 2) fused init + unit-scheduled GEMM on all 148 SMs
    gemm_kernel<<<NCTA, NTHREADS, SMEM_TOTAL>>>(
        x, W, b, coeff, idx, bitpos, out);
}

// round 15
// speedup vs baseline: 1.4546x; 1.3177x over previous
#include <cuda_runtime.h>
#include <cuda_fp16.h>
#include <cstdint>
#include <cstddef>

// ---------------------------------------------------------------------------
// out[B,O] = (x + sparse_pert) @ W + b
//          = x @ W + b + coeff * u[r] * W[idx[r], :]   (u = bitflip(g) - g)
// B=4096, F=16384, O=256, fp32.
//
// R15: R11 structure (best: 160.5us; R13/R14 multi-tile scheduling regressed).
// Changes: (1) Wt kept k-major ([k][n], same layout as W) -> prep_w is a pure
// streaming convert (~4us vs 8.4); B fragments via ldmatrix.x4.trans on the
// k-major tile (pitch 528B, conflict-free). (2) fused init moved after the
// prologue cp.async issues to overlap stage-0..3 DRAM latency.
// ---------------------------------------------------------------------------

namespace {
constexpr int Bm = 4096;
constexpr int Fk = 16384;
constexpr int On = 256;

constexpr int BM = 128;
constexpr int BK = 32;
constexpr int SPLITK = 4;
constexpr int K_PER_CTA = Fk / SPLITK;     // 4096
constexpr int NT = K_PER_CTA / BK;         // 128 stages
constexpr int STAGES = 5;
constexpr int NTHREADS = 256;

// SMEM layout (bytes)
constexpr int RAWA_STAGE = BM * BK * 4;            // 16384 (fp32 x tile)
constexpr int BROW_PITCH = 80;                     // A conv rows: 64B + pad
constexpr int BPITCH = 528;                        // B k-major rows: 512B + 16
constexpr int B_STAGE = BK * BPITCH;               // 16896
constexpr int ACONV = BM * BROW_PITCH;             // 10240 (x2 parity)

constexpr int OFF_RAWA = 0;                                        // 81920
constexpr int OFF_B    = OFF_RAWA + STAGES * RAWA_STAGE;           // 81920
constexpr int OFF_AC   = OFF_B + STAGES * B_STAGE;                 // 166400
constexpr int SMEM_TOTAL = OFF_AC + 2 * ACONV;                     // 186880
}  // namespace

// W in fp16, SAME layout as W: [F][O], n contiguous. 8 MB static scratch.
__device__ __align__(16) __half g_Wt[(size_t)Fk * On];

// ---------------------------- helpers --------------------------------------
__device__ __forceinline__ uint32_t smem_u32(const void* p) {
    uint32_t a;
    asm("{ .reg .u64 t; cvta.to.shared.u64 t, %1; cvt.u32.u64 %0, t; }"
        : "=r"(a) : "l"(p));
    return a;
}

__device__ __forceinline__ void cp_async16(void* dst, const void* src) {
    asm volatile("cp.async.cg.shared.global [%0], [%1], 16;"
                 :: "r"(smem_u32(dst)), "l"(src) : "memory");
}
__device__ __forceinline__ void cp_commit() {
    asm volatile("cp.async.commit_group;" ::: "memory");
}
template <int N>
__device__ __forceinline__ void cp_wait() {
    asm volatile("cp.async.wait_group %0;" :: "n"(N) : "memory");
}

// pack f16(x1):f16(x0), x0 in low half
__device__ __forceinline__ uint32_t cvt_f16x2(float x1, float x0) {
    uint32_t d;
    asm("cvt.rn.f16x2.f32 %0, %1, %2;" : "=r"(d) : "f"(x1), "f"(x0));
    return d;
}

__device__ __forceinline__ void ldsm_x4(uint32_t r[4], uint32_t addr) {
    asm volatile(
        "ldmatrix.sync.aligned.m8n8.x4.shared.b16 {%0,%1,%2,%3}, [%4];"
        : "=r"(r[0]), "=r"(r[1]), "=r"(r[2]), "=r"(r[3]) : "r"(addr));
}

__device__ __forceinline__ void ldsm_x4_trans(uint32_t r[4], uint32_t addr) {
    asm volatile(
        "ldmatrix.sync.aligned.m8n8.x4.trans.shared.b16 {%0,%1,%2,%3}, [%4];"
        : "=r"(r[0]), "=r"(r[1]), "=r"(r[2]), "=r"(r[3]) : "r"(addr));
}

__device__ __forceinline__ void mma_f16(float c[4], const uint32_t a[4],
                                        const uint32_t b[2]) {
    asm volatile(
        "mma.sync.aligned.m16n8k16.row.col.f32.f16.f16.f32 "
        "{%0,%1,%2,%3},{%4,%5,%6,%7},{%8,%9},{%0,%1,%2,%3};"
        : "+f"(c[0]), "+f"(c[1]), "+f"(c[2]), "+f"(c[3])
        : "r"(a[0]), "r"(a[1]), "r"(a[2]), "r"(a[3]), "r"(b[0]), "r"(b[1]));
}

// -------- kernel 1: W fp32 -> fp16, identity layout (pure stream) ----------
__global__ void prep_w_kernel(const float* __restrict__ W) {
    size_t i = ((size_t)blockIdx.x * 256 + threadIdx.x) * 8;
    float4 v0 = *(const float4*)(W + i);
    float4 v1 = *(const float4*)(W + i + 4);
    uint4 o;
    o.x = cvt_f16x2(v0.y, v0.x);
    o.y = cvt_f16x2(v0.w, v0.z);
    o.z = cvt_f16x2(v1.y, v1.x);
    o.w = cvt_f16x2(v1.w, v1.z);
    *(uint4*)(g_Wt + i) = o;
}

// ------------ kernel 2: fused init + split-K fp16 mma.sync GEMM ------------
__global__ void __launch_bounds__(NTHREADS, 1)
gemm_kernel(const float* __restrict__ x, const float* __restrict__ W,
            const float* __restrict__ b, const float* __restrict__ coeff,
            const int* __restrict__ idx, const int* __restrict__ bitpos,
            float* __restrict__ out) {
    extern __shared__ char smem[];
    __shared__ float us[32];
    char* rawA = smem + OFF_RAWA;
    char* BS   = smem + OFF_B;
    char* Ac   = smem + OFF_AC;   // 2 parity buffers of ACONV bytes

    const int tid = threadIdx.x;
    const int lane = tid & 31, w = tid >> 5;
    const int wm = w & 1, wn = w >> 1;       // warp grid 2(M) x 4(N), 64x64 tile
    const int g = lane >> 2, q = lane & 3;

    const int m0 = blockIdx.x * BM;
    const int z  = blockIdx.z;
    const int kbase = z * K_PER_CTA;

    // ---- stage loader (always commits one group) ----
    auto issue = [&](int kt, int slot) {
        if (kt < NT) {
            const float* xg = x + (size_t)m0 * Fk + kbase + kt * BK;
            char* ra = rawA + slot * RAWA_STAGE;
#pragma unroll
            for (int i = 0; i < 4; i++) {
                int ch = tid + i * NTHREADS;      // 0..1023
                int row = ch >> 3, sub = ch & 7;
                int phys = sub ^ (row & 7);       // XOR swizzle (bank-free reads)
                cp_async16(ra + row * 128 + phys * 16,
                           xg + (size_t)row * Fk + sub * 4);
            }
            // B: k-major Wt rows [kbase+kt*BK .. +32), each 512B contiguous
            const __half* wt = g_Wt + (size_t)(kbase + kt * BK) * On;
            char* bs = BS + slot * B_STAGE;
#pragma unroll
            for (int i = 0; i < 4; i++) {
                int ch = tid + i * NTHREADS;      // 0..1023
                int row = ch >> 5, sub = ch & 31; // row 0..31 (k), sub 16B
                cp_async16(bs + row * BPITCH + sub * 16,
                           wt + (size_t)row * On + sub * 8);
            }
        }
        cp_commit();
    };

    // ---- prologue loads FIRST: their DRAM latency covers the init below ---
    issue(0, 0); issue(1, 1); issue(2, 2); issue(3, 3);

    // ---- fused init: rows [m0+32z, m0+32z+32) of out = b + coeff*u*W[idx]
    // Single wave (128 CTAs <= 148 SMs at occ 1): init done ~2us in; first
    // epilogue atomic lands ~150us later.
    {
        int r0 = m0 + z * 32;
        if (tid < 32) {
            int r = r0 + tid;
            int j = idx[r];
            float gg = x[(size_t)r * Fk + j];
            int gi = __float_as_int(gg) ^ (1 << bitpos[r]);
            us[tid] = (__int_as_float(gi) - gg) * coeff[0];
        }
        __syncthreads();
#pragma unroll
        for (int i = 0; i < 32; i++) {
            int e = tid + i * NTHREADS;
            int rr = e >> 8, c = e & 255;
            int r = r0 + rr;
            out[(size_t)r * On + c] =
                b[c] + us[rr] * W[(size_t)idx[r] * On + c];
        }
    }

    // ldmatrix per-lane address components
    const int lrow = lane & 15;              // A: row within 16
    const int lk16 = (lane >> 4) * 16;       // A: k-16B half
    const int bRow = (lane & 7) + ((lane >> 3) & 1) * 8;  // B: k row 0..15
    const int bNb  = (lane >> 4) * 16;       // B: +8n (16 bytes)

    float acc[4][8][4];
#pragma unroll
    for (int i = 0; i < 4; i++)
#pragma unroll
        for (int j = 0; j < 8; j++)
#pragma unroll
            for (int r = 0; r < 4; r++) acc[i][j][r] = 0.0f;

    // convert-thread mapping: conflict-free LDS.128 + STS.128 (half-row/thr)
    const int crow = (w & 3) * 32 + lane;   // 0..127
    const int chh  = w >> 2;                // half of the 32-float row

    auto convert = [&](int k) {             // rawA slot k%5 -> Ac[k&1]
        const char* ra = rawA + (k % STAGES) * RAWA_STAGE;
        char* dst = Ac + (k & 1) * ACONV;
        uint32_t pk[8];
#pragma unroll
        for (int i = 0; i < 4; i++) {
            int phys = (chh * 4 + i) ^ (crow & 7);
            float4 v = *(const float4*)(ra + crow * 128 + phys * 16);
            pk[i * 2]     = cvt_f16x2(v.y, v.x);
            pk[i * 2 + 1] = cvt_f16x2(v.w, v.z);
        }
        uint4* d = (uint4*)(dst + crow * BROW_PITCH + chh * 32);
        d[0] = make_uint4(pk[0], pk[1], pk[2], pk[3]);
        d[1] = make_uint4(pk[4], pk[5], pk[6], pk[7]);
    };

    cp_wait<3>();            // group 0 complete
    __syncthreads();         // visible to all
    convert(0);              // Ac[0] <- stage 0

    // ---- mainloop: ONE barrier per stage; convert(kt+1) overlaps MMA(kt) --
    int pslot = 4;           // slot for prefetch stage kt+4
    for (int kt = 0; kt < NT; kt++) {
        cp_wait<2>();        // committed 4+kt; group kt+1 complete
        __syncthreads();     // loads visible; prev MMA+convert done (reuse)

        issue(kt + 4, pslot);
        if (++pslot == STAGES) pslot = 0;

        // MMA on stage kt (Ac[kt&1], BS slot kt%5)
        const uint32_t aBase = smem_u32(Ac) + (kt & 1) * ACONV +
            (wm * 64 + lrow) * BROW_PITCH + lk16;
        // B base: k-major tile; per-lane row bRow, n offset wn*64 (+8n sel)
        const uint32_t bBase = smem_u32(BS) + (kt % STAGES) * B_STAGE +
            bRow * BPITCH + (wn * 64) * 2 + bNb;
#pragma unroll
        for (int kk = 0; kk < 2; kk++) {
            uint32_t af[4][4];
#pragma unroll
            for (int mt = 0; mt < 4; mt++)
                ldsm_x4(af[mt], aBase + mt * 16 * BROW_PITCH + kk * 32);
            uint32_t bf[8][2];
#pragma unroll
            for (int p = 0; p < 4; p++) {
                uint32_t r[4];
                // 16k x 16n region at (kk*16, p*16): transposed load
                ldsm_x4_trans(r, bBase + kk * 16 * BPITCH + p * 32);
                bf[2 * p][0] = r[0]; bf[2 * p][1] = r[1];
                bf[2 * p + 1][0] = r[2]; bf[2 * p + 1][1] = r[3];
            }
#pragma unroll
            for (int mt = 0; mt < 4; mt++)
#pragma unroll
                for (int nt = 0; nt < 8; nt++)
                    mma_f16(acc[mt][nt], af[mt], bf[nt]);
        }

        // convert NEXT stage's A while this stage's MMAs drain
        if (kt + 1 < NT) convert(kt + 1);
    }

    cp_wait<0>();  // drain outstanding cp.async before exit

    // ---- epilogue: atomicAdd into initialized out ----
#pragma unroll
    for (int mt = 0; mt < 4; mt++) {
        int r0 = m0 + wm * 64 + mt * 16 + g;
#pragma unroll
        for (int nt = 0; nt < 8; nt++) {
            int col = wn * 64 + nt * 8 + q * 2;
            float* p0 = out + (size_t)r0 * On + col;
            float* p1 = out + (size_t)(r0 + 8) * On + col;
            atomicAdd(p0,     acc[mt][nt][0]);
            atomicAdd(p0 + 1, acc[mt][nt][1]);
            atomicAdd(p1,     acc[mt][nt][2]);
            atomicAdd(p1 + 1, acc[mt][nt][3]);
        }
    }
}

// ---------------------------------------------------------------------------
extern "C" void kernel_launch(void* const* d_in, const int* in_sizes, int n_in,
                              void* d_out, int out_size) {
    const float* x      = (const float*)d_in[0];
    const float* W      = (const float*)d_in[1];
    const float* b      = (const float*)d_in[2];
    const float* coeff  = (const float*)d_in[3];
    const int*   idx    = (const int*)d_in[4];
    const int*   bitpos = (const int*)d_in[5];
    float* out = (float*)d_out;

    cudaFuncSetAttribute(gemm_kernel,
                         cudaFuncAttributeMaxDynamicSharedMemorySize,
                         SMEM_TOTAL);

    // 1) W -> fp16 (identity layout, streaming): 4M elems / (256 thr * 8)
    prep_w_kernel<<<(Fk * On) / (256 * 8), 256>>>(W);
    // 2) fused init (rank-1 correction + bias) + split-K GEMM
    gemm_kernel<<<dim3(Bm / BM, 1, SPLITK), NTHREADS, SMEM_TOTAL>>>(
        x, W, b, coeff, idx, bitpos, out);
}